// round 14
// baseline (speedup 1.0000x reference)
#include <cuda_runtime.h>
#include <cuda_bf16.h>
#include <float.h>
#include <stdint.h>

#define NPTS 8192
#define KNB  8
#define H0D  64
#define H1D  128
#define OUTC 256
#define SA   40          // smem row stride (bf16) -> conflict-free fragment LDS
#define NSLICE 4
#define SLICE  2048      // candidates per knn slice
#define BUFCAP 96        // survivor buffer per (query, slice)

// ---------------- scratch (static device globals) ----------------
__device__ int   g_idx[NPTS * KNB];
__device__ float g_a1[NPTS * H0D];
__device__ float g_c1[NPTS * H0D];
__device__ float g_x1[NPTS * H1D];
__device__ float g_a2[NPTS * H1D];
__device__ float g_c2[NPTS * H1D];
__device__ float g_pd[NPTS * NSLICE * KNB];   // knn per-slice partial dists
__device__ int   g_pi[NPTS * NSLICE * KNB];   // knn per-slice partial idx

// weights: bf16 hi/lo split, transposed to [N][K]
__device__ __nv_bfloat16 g_w2t_hi[H1D * H0D],     g_w2t_lo[H1D * H0D];      // [128][64]
__device__ __nv_bfloat16 g_w3t_hi[2 * H1D * H1D], g_w3t_lo[2 * H1D * H1D];  // [2][128][128]
__device__ __nv_bfloat16 g_w4t_hi[OUTC * H1D],    g_w4t_lo[OUTC * H1D];     // [256][128]

// ---------------- helpers ----------------
__device__ __forceinline__ void bsplit(float v, __nv_bfloat16& h, __nv_bfloat16& l) {
    h = __float2bfloat16_rn(v);
    l = __float2bfloat16_rn(v - __bfloat162float(h));
}

__device__ __forceinline__ void mma16816(float* c, const uint32_t* a, const uint32_t* b) {
    asm volatile(
        "mma.sync.aligned.m16n8k16.row.col.f32.bf16.bf16.f32 "
        "{%0,%1,%2,%3}, {%4,%5,%6,%7}, {%8,%9}, {%0,%1,%2,%3};\n"
        : "+f"(c[0]), "+f"(c[1]), "+f"(c[2]), "+f"(c[3])
        : "r"(a[0]), "r"(a[1]), "r"(a[2]), "r"(a[3]), "r"(b[0]), "r"(b[1]));
}

// ---------------------------------------------------------------------------
// weight prep (split in two so knnA lands as the 4th launch -> ncu capture)
// ---------------------------------------------------------------------------
__global__ void prep_w2k(const float* __restrict__ W2) {
    int t = blockIdx.x * 256 + threadIdx.x;      // 8192 = 128n * 64k
    int n = t >> 6, k = t & 63;
    bsplit(W2[k * H1D + n], g_w2t_hi[t], g_w2t_lo[t]);
}
__global__ void prep_w34(const float* __restrict__ W3,
                         const float* __restrict__ W4) {
    int t = blockIdx.x * 256 + threadIdx.x;      // 65536 total
    if (t < 32768) {
        int half = t >> 14; int rr = t & 16383; int n = rr >> 7; int k = rr & 127;
        float v = W3[(H1D + k) * H1D + n];
        if (half == 0) v = W3[k * H1D + n] - v;
        bsplit(v, g_w3t_hi[t], g_w3t_lo[t]);
    } else {
        int r = t - 32768;
        int n = r >> 7, k = r & 127;
        bsplit(W4[k * OUTC + n], g_w4t_hi[r], g_w4t_lo[r]);
    }
}

// ---------------------------------------------------------------------------
// pre1: a1[i] = x_i @ (W1a - W1b) + b1 ; c1[j] = x_j @ W1b
// ---------------------------------------------------------------------------
__global__ void pre1_kernel(const float* __restrict__ pts,
                            const float* __restrict__ W1,
                            const float* __restrict__ b1) {
    int t = blockIdx.x * blockDim.x + threadIdx.x;
    int i = t >> 6, h = t & 63;
    float x = pts[i * 3 + 0], y = pts[i * 3 + 1], z = pts[i * 3 + 2];
    float wa0 = W1[0 * 64 + h], wa1 = W1[1 * 64 + h], wa2 = W1[2 * 64 + h];
    float wb0 = W1[3 * 64 + h], wb1 = W1[4 * 64 + h], wb2 = W1[5 * 64 + h];
    float c = fmaf(z, wb2, fmaf(y, wb1, x * wb0));
    float a = fmaf(z, wa2 - wb2, fmaf(y, wa1 - wb1, x * (wa0 - wb0))) + b1[h];
    g_a1[t] = a;
    g_c1[t] = c;
}

// ---------------------------------------------------------------------------
// KNN stage A v3: grid (256 query-tiles x 4 slices), block 256 = 32q x 8sh.
// Pass 1: branchless shard-min -> tau (>= slice 8th distance).
// Pass 2: BRANCH-FREE survivor compaction. Per warp-iteration:
//   m = ballot(d<=tau); each query's 8-bit field of m gives this lane's
//   buffer slot via popc-prefix and the (uniform) register counter bump.
//   Stores are predicated STS; no atomics, no divergent branches.
//   Survivor set identical to the atomic version (d<=tau), and the finish
//   sorted lex-insert over a superset is order-independent -> identical
//   g_idx and tie semantics (matches jax top_k).
// ---------------------------------------------------------------------------
__global__ void __launch_bounds__(256)
knnA_kernel(const float* __restrict__ pts) {
    __shared__ float4 sP[SLICE];              // 32 KB
    __shared__ float  sBd[32][BUFCAP];        // 12 KB
    __shared__ int    sBi[32][BUFCAP];        // 12 KB
    __shared__ int    sCnt[32];

    const int tid = threadIdx.x;
    const int ql = tid >> 3, sh = tid & 7;
    const int qiw = (tid >> 3) & 3;           // query index within warp
    const int q = blockIdx.x * 32 + ql;
    const int c0 = blockIdx.y * SLICE;

    for (int j = tid; j < SLICE; j += 256) {
        float x = pts[(c0 + j) * 3 + 0];
        float y = pts[(c0 + j) * 3 + 1];
        float z = pts[(c0 + j) * 3 + 2];
        sP[j] = make_float4(x, y, z, fmaf(z, z, fmaf(y, y, x * x)));
    }
    const float qx = pts[q * 3 + 0], qy = pts[q * 3 + 1], qz = pts[q * 3 + 2];
    const float qx2 = -2.0f * qx, qy2 = -2.0f * qy, qz2 = -2.0f * qz;
    __syncthreads();

    // ---- pass 1: branchless shard min ----
    float mymin = FLT_MAX;
#pragma unroll 8
    for (int i = 0; i < SLICE / 8; ++i) {
        float4 p = sP[i * 8 + sh];
        float d = fmaf(qz2, p.z, fmaf(qy2, p.y, fmaf(qx2, p.x, p.w)));
        mymin = fminf(mymin, d);
    }
    float tau = mymin;
    tau = fmaxf(tau, __shfl_xor_sync(0xffffffffu, tau, 1));
    tau = fmaxf(tau, __shfl_xor_sync(0xffffffffu, tau, 2));
    tau = fmaxf(tau, __shfl_xor_sync(0xffffffffu, tau, 4));

    // ---- pass 2: branch-free ballot-prefix compaction ----
    const unsigned ltm = (1u << sh) - 1u;     // earlier-shard mask within query byte
    int cnt = 0;
#pragma unroll 8
    for (int i = 0; i < SLICE / 8; ++i) {
        int jj = i * 8 + sh;
        float4 p = sP[jj];
        float d = fmaf(qz2, p.z, fmaf(qy2, p.y, fmaf(qx2, p.x, p.w)));
        bool keep = (d <= tau);
        unsigned m = __ballot_sync(0xffffffffu, keep);
        unsigned mq = (m >> (qiw * 8)) & 0xffu;
        int slot = cnt + __popc(mq & ltm);
        if (keep && slot < BUFCAP) {          // predicated STS pair (no branch)
            sBd[ql][slot] = d;
            sBi[ql][slot] = c0 + jj;
        }
        cnt += __popc(mq);                    // uniform across the query's lanes
    }
    if (sh == 0) sCnt[ql] = cnt;
    __syncthreads();

    // ---- finish: one thread per query lex-inserts its survivors ----
    if (tid < 32) {
        int cnt2 = sCnt[tid]; if (cnt2 > BUFCAP) cnt2 = BUFCAP;
        float md[KNB]; int mi[KNB];
#pragma unroll
        for (int s = 0; s < KNB; ++s) { md[s] = FLT_MAX; mi[s] = 0x7fffffff; }
        for (int e = 0; e < cnt2; ++e) {
            float d = sBd[tid][e]; int i = sBi[tid][e];
            if (d < md[KNB - 1] || (d == md[KNB - 1] && i < mi[KNB - 1])) {
                md[KNB - 1] = d; mi[KNB - 1] = i;
#pragma unroll
                for (int s = KNB - 1; s > 0; --s) {
                    if (md[s] < md[s - 1] || (md[s] == md[s - 1] && mi[s] < mi[s - 1])) {
                        float td = md[s]; md[s] = md[s - 1]; md[s - 1] = td;
                        int   ti = mi[s]; mi[s] = mi[s - 1]; mi[s - 1] = ti;
                    } else break;
                }
            }
        }
        int qq = blockIdx.x * 32 + tid;
        int base = qq * (NSLICE * KNB) + blockIdx.y * KNB;
#pragma unroll
        for (int s = 0; s < KNB; ++s) { g_pd[base + s] = md[s]; g_pi[base + s] = mi[s]; }
    }
}

// ---------------------------------------------------------------------------
// KNN stage B: one thread per query merges the 4 slice top-8s (lex order).
// ---------------------------------------------------------------------------
__global__ void knnB_kernel() {
    int q = blockIdx.x * 256 + threadIdx.x;
    float md[KNB]; int mi[KNB];
#pragma unroll
    for (int s = 0; s < KNB; ++s) { md[s] = FLT_MAX; mi[s] = 0x7fffffff; }
    int base = q * (NSLICE * KNB);
    for (int e = 0; e < NSLICE * KNB; ++e) {
        float d = g_pd[base + e]; int i = g_pi[base + e];
        if (d < md[KNB - 1] || (d == md[KNB - 1] && i < mi[KNB - 1])) {
            md[KNB - 1] = d; mi[KNB - 1] = i;
#pragma unroll
            for (int s = KNB - 1; s > 0; --s) {
                if (md[s] < md[s - 1] || (md[s] == md[s - 1] && mi[s] < mi[s - 1])) {
                    float td = md[s]; md[s] = md[s - 1]; md[s - 1] = td;
                    int   ti = mi[s]; mi[s] = mi[s - 1]; mi[s - 1] = ti;
                } else break;
            }
        }
    }
#pragma unroll
    for (int s = 0; s < KNB; ++s) g_idx[q * KNB + s] = mi[s];
}

// ===========================================================================
// Tensor-core edge GEMM (unchanged from round 6/7).
// ===========================================================================

#define GEMM_CORE(KDIM, A_BUILD)                                                   \
    const int tid = threadIdx.x;                                                   \
    const int lane = tid & 31, wid = tid >> 5;                                     \
    const int g = lane >> 2, tig = lane & 3;                                       \
    const int wm = wid & 3, wn = wid >> 2;                                         \
    const int fm = tid & 127, fq = tid >> 7;                                       \
    float acc[2][8][4];                                                            \
    _Pragma("unroll") for (int mb = 0; mb < 2; ++mb)                               \
    _Pragma("unroll") for (int nt = 0; nt < 8; ++nt)                               \
    _Pragma("unroll") for (int e = 0; e < 4; ++e) acc[mb][nt][e] = 0.f;            \
    for (int kb = 0; kb < (KDIM); kb += 32) {                                      \
        { A_BUILD }                                                                \
        {   /* stage B: [n][k] rows, 16 bf16 per thread per buffer */              \
            const __nv_bfloat16* bh = Bhi_g + fm * (KDIM) + kb + fq * 16;          \
            const __nv_bfloat16* bl = Blo_g + fm * (KDIM) + kb + fq * 16;          \
            int o = fm * SA + fq * 16;                                             \
            *(uint4*)&sBhi[o]     = *(const uint4*)(bh);                           \
            *(uint4*)&sBhi[o + 8] = *(const uint4*)(bh + 8);                       \
            *(uint4*)&sBlo[o]     = *(const uint4*)(bl);                           \
            *(uint4*)&sBlo[o + 8] = *(const uint4*)(bl + 8);                       \
        }                                                                          \
        __syncthreads();                                                           \
        _Pragma("unroll")                                                          \
        for (int ks = 0; ks < 2; ++ks) {                                           \
            const int kc = ks * 16;                                                \
            _Pragma("unroll")                                                      \
            for (int t = 0; t < 3; ++t) {                                          \
                const __nv_bfloat16* Ap = (t == 2) ? sAlo : sAhi;                  \
                const __nv_bfloat16* Bp = (t == 1) ? sBlo : sBhi;                  \
                uint32_t af[2][4];                                                 \
                _Pragma("unroll")                                                  \
                for (int mb = 0; mb < 2; ++mb) {                                   \
                    int r = (wm * 32 + mb * 16 + g) * SA + kc + tig * 2;           \
                    af[mb][0] = *(const uint32_t*)(Ap + r);                        \
                    af[mb][1] = *(const uint32_t*)(Ap + r + 8 * SA);               \
                    af[mb][2] = *(const uint32_t*)(Ap + r + 8);                    \
                    af[mb][3] = *(const uint32_t*)(Ap + r + 8 * SA + 8);           \
                }                                                                  \
                uint32_t bf[8][2];                                                 \
                _Pragma("unroll")                                                  \
                for (int nt = 0; nt < 8; ++nt) {                                   \
                    int rB = (wn * 64 + nt * 8 + g) * SA + kc + tig * 2;           \
                    bf[nt][0] = *(const uint32_t*)(Bp + rB);                       \
                    bf[nt][1] = *(const uint32_t*)(Bp + rB + 8);                   \
                }                                                                  \
                _Pragma("unroll")                                                  \
                for (int mb = 0; mb < 2; ++mb)                                     \
                _Pragma("unroll")                                                  \
                for (int nt = 0; nt < 8; ++nt)                                     \
                    mma16816(acc[mb][nt], af[mb], bf[nt]);                         \
            }                                                                      \
        }                                                                          \
        __syncthreads();                                                           \
    }

#define EDGE_A_BUILD(KDIM, ASRC, CSRC)                                             \
    const float* __restrict__ arow = (ASRC) + (p0 + (fm >> 3)) * (KDIM);           \
    const float* __restrict__ crow = (CSRC) + sIdx[fm] * (KDIM);                   \
    _Pragma("unroll")                                                              \
    for (int u = 0; u < 4; ++u) {                                                  \
        float4 a = *(const float4*)(arow + kb + fq * 16 + u * 4);                  \
        float4 c = *(const float4*)(crow + kb + fq * 16 + u * 4);                  \
        float v0 = fmaxf(a.x + c.x, 0.f), v1 = fmaxf(a.y + c.y, 0.f);              \
        float v2 = fmaxf(a.z + c.z, 0.f), v3 = fmaxf(a.w + c.w, 0.f);              \
        __nv_bfloat16 h0, l0, h1, l1, h2, l2, h3, l3;                              \
        bsplit(v0, h0, l0); bsplit(v1, h1, l1);                                    \
        bsplit(v2, h2, l2); bsplit(v3, h3, l3);                                    \
        int o = fm * SA + fq * 16 + u * 4;                                         \
        __nv_bfloat162 p01; p01.x = h0; p01.y = h1;                                \
        __nv_bfloat162 p23; p23.x = h2; p23.y = h3;                                \
        *(__nv_bfloat162*)&sAhi[o] = p01; *(__nv_bfloat162*)&sAhi[o + 2] = p23;    \
        p01.x = l0; p01.y = l1; p23.x = l2; p23.y = l3;                            \
        *(__nv_bfloat162*)&sAlo[o] = p01; *(__nv_bfloat162*)&sAlo[o + 2] = p23;    \
    }

#define EDGE_POOL_EPILOGUE()                                                       \
    _Pragma("unroll")                                                              \
    for (int mb = 0; mb < 2; ++mb)                                                 \
    _Pragma("unroll")                                                              \
    for (int nt = 0; nt < 8; ++nt)                                                 \
    _Pragma("unroll")                                                              \
    for (int e = 0; e < 4; ++e) {                                                  \
        float v = acc[mb][nt][e];                                                  \
        v = fmaxf(v, __shfl_xor_sync(0xffffffffu, v, 4));                          \
        v = fmaxf(v, __shfl_xor_sync(0xffffffffu, v, 8));                          \
        v = fmaxf(v, __shfl_xor_sync(0xffffffffu, v, 16));                         \
        acc[mb][nt][e] = v;                                                        \
    }                                                                              \
    if (g == 0) {                                                                  \
        _Pragma("unroll")                                                          \
        for (int mb = 0; mb < 2; ++mb)                                             \
        _Pragma("unroll")                                                          \
        for (int nt = 0; nt < 8; ++nt)                                             \
        _Pragma("unroll")                                                          \
        for (int e = 0; e < 4; ++e) {                                              \
            int point = wm * 4 + mb * 2 + (e >> 1);                                \
            int col = wn * 64 + nt * 8 + tig * 2 + (e & 1);                        \
            sRed[point * 132 + col] = acc[mb][nt][e];                              \
        }                                                                          \
    }                                                                              \
    __syncthreads();

// ---------------------------------------------------------------------------
// edge1: x1 = relu( max_k relu(a1[i]+c1[j]) @ W2 + b2 );  K=64, N=128
// ---------------------------------------------------------------------------
__global__ void __launch_bounds__(256, 2)
edge1_kernel(const float* __restrict__ b2) {
    __shared__ __align__(16) char smraw[4 * 128 * SA * 2];
    __shared__ int sIdx[128];
    __nv_bfloat16* sAhi = (__nv_bfloat16*)smraw;
    __nv_bfloat16* sAlo = sAhi + 128 * SA;
    __nv_bfloat16* sBhi = sAlo + 128 * SA;
    __nv_bfloat16* sBlo = sBhi + 128 * SA;
    float* sRed = (float*)smraw;                   // reused after GEMM

    const int p0 = blockIdx.x * 16;
    if (threadIdx.x < 128) sIdx[threadIdx.x] = g_idx[p0 * KNB + threadIdx.x];
    __syncthreads();

    const __nv_bfloat16* Bhi_g = g_w2t_hi;
    const __nv_bfloat16* Blo_g = g_w2t_lo;

    GEMM_CORE(64, EDGE_A_BUILD(64, g_a1, g_c1))
    EDGE_POOL_EPILOGUE()

    for (int r = tid; r < 2048; r += 256) {
        int p = r >> 7, c = r & 127;
        g_x1[(p0 + p) * H1D + c] = fmaxf(sRed[p * 132 + c] + b2[c], 0.f);
    }
}

// ---------------------------------------------------------------------------
// pre2: a2 = x1 @ (W3a-W3b) + b3 ; c2 = x1 @ W3b.  M=128, N=128, K=128.
// ---------------------------------------------------------------------------
#define PRE2_A_BUILD()                                                             \
    const float* __restrict__ xrow = g_x1 + (r0 + fm) * H1D;                       \
    _Pragma("unroll")                                                              \
    for (int u = 0; u < 4; ++u) {                                                  \
        float4 a = *(const float4*)(xrow + kb + fq * 16 + u * 4);                  \
        __nv_bfloat16 h0, l0, h1, l1, h2, l2, h3, l3;                              \
        bsplit(a.x, h0, l0); bsplit(a.y, h1, l1);                                  \
        bsplit(a.z, h2, l2); bsplit(a.w, h3, l3);                                  \
        int o = fm * SA + fq * 16 + u * 4;                                         \
        __nv_bfloat162 p01; p01.x = h0; p01.y = h1;                                \
        __nv_bfloat162 p23; p23.x = h2; p23.y = h3;                                \
        *(__nv_bfloat162*)&sAhi[o] = p01; *(__nv_bfloat162*)&sAhi[o + 2] = p23;    \
        p01.x = l0; p01.y = l1; p23.x = l2; p23.y = l3;                            \
        *(__nv_bfloat162*)&sAlo[o] = p01; *(__nv_bfloat162*)&sAlo[o + 2] = p23;    \
    }

__global__ void __launch_bounds__(256, 2)
pre2_kernel(const float* __restrict__ b3) {
    __shared__ __align__(16) char smraw[4 * 128 * SA * 2];
    __nv_bfloat16* sAhi = (__nv_bfloat16*)smraw;
    __nv_bfloat16* sAlo = sAhi + 128 * SA;
    __nv_bfloat16* sBhi = sAlo + 128 * SA;
    __nv_bfloat16* sBlo = sBhi + 128 * SA;

    const int r0 = blockIdx.x * 128;
    const int half = blockIdx.y;
    const __nv_bfloat16* Bhi_g = g_w3t_hi + half * (H1D * H1D);
    const __nv_bfloat16* Blo_g = g_w3t_lo + half * (H1D * H1D);

    GEMM_CORE(128, PRE2_A_BUILD())

    float* __restrict__ outp = half ? g_c2 : g_a2;
#pragma unroll
    for (int mb = 0; mb < 2; ++mb) {
        int row = r0 + wm * 32 + mb * 16 + g;
#pragma unroll
        for (int nt = 0; nt < 8; ++nt) {
            int col = wn * 64 + nt * 8 + tig * 2;
            float bx = half ? 0.f : b3[col];
            float by = half ? 0.f : b3[col + 1];
            float2 v0 = make_float2(acc[mb][nt][0] + bx, acc[mb][nt][1] + by);
            float2 v1 = make_float2(acc[mb][nt][2] + bx, acc[mb][nt][3] + by);
            *(float2*)&outp[row * H1D + col] = v0;
            *(float2*)&outp[(row + 8) * H1D + col] = v1;
        }
    }
}

// ---------------------------------------------------------------------------
// edge2: out = max_k relu(a2[i]+c2[j]) @ W4 + b4.  K=128, N=256 (split by y).
// ---------------------------------------------------------------------------
__global__ void __launch_bounds__(256, 2)
edge2_kernel(const float* __restrict__ b4, float* __restrict__ out) {
    __shared__ __align__(16) char smraw[4 * 128 * SA * 2];
    __shared__ int sIdx[128];
    __nv_bfloat16* sAhi = (__nv_bfloat16*)smraw;
    __nv_bfloat16* sAlo = sAhi + 128 * SA;
    __nv_bfloat16* sBhi = sAlo + 128 * SA;
    __nv_bfloat16* sBlo = sBhi + 128 * SA;
    float* sRed = (float*)smraw;

    const int p0 = blockIdx.x * 16;
    const int nb = blockIdx.y * 128;
    if (threadIdx.x < 128) sIdx[threadIdx.x] = g_idx[p0 * KNB + threadIdx.x];
    __syncthreads();

    const __nv_bfloat16* Bhi_g = g_w4t_hi + nb * H1D;
    const __nv_bfloat16* Blo_g = g_w4t_lo + nb * H1D;

    GEMM_CORE(128, EDGE_A_BUILD(128, g_a2, g_c2))
    EDGE_POOL_EPILOGUE()

    for (int r = tid; r < 2048; r += 256) {
        int p = r >> 7, c = r & 127;
        out[(p0 + p) * OUTC + nb + c] = sRed[p * 132 + c] + b4[nb + c];
    }
}

// ---------------------------------------------------------------------------
extern "C" void kernel_launch(void* const* d_in, const int* in_sizes, int n_in,
                              void* d_out, int out_size) {
    const float* pts = (const float*)d_in[0];
    const float* W1  = (const float*)d_in[1];
    const float* b1  = (const float*)d_in[2];
    const float* W2  = (const float*)d_in[3];
    const float* b2  = (const float*)d_in[4];
    const float* W3  = (const float*)d_in[5];
    const float* b3  = (const float*)d_in[6];
    const float* W4  = (const float*)d_in[7];
    const float* b4  = (const float*)d_in[8];
    float* out = (float*)d_out;

    prep_w2k<<<32, 256>>>(W2);                         // 1
    prep_w34<<<256, 256>>>(W3, W4);                    // 2
    pre1_kernel<<<NPTS * H0D / 256, 256>>>(pts, W1, b1); // 3
    knnA_kernel<<<dim3(NPTS / 32, NSLICE), 256>>>(pts);  // 4 <- ncu capture slot
    knnB_kernel<<<NPTS / 256, 256>>>();                // 5
    edge1_kernel<<<NPTS / 16, 256>>>(b2);              // 6
    pre2_kernel<<<dim3(NPTS / 128, 2), 256>>>(b3);     // 7
    edge2_kernel<<<dim3(NPTS / 16, 2), 256>>>(b4, out);// 8
}

// round 15
// speedup vs baseline: 1.1769x; 1.1769x over previous
#include <cuda_runtime.h>
#include <cuda_bf16.h>
#include <float.h>
#include <stdint.h>

#define NPTS 8192
#define KNB  8
#define H0D  64
#define H1D  128
#define OUTC 256
#define SA   40          // smem row stride (bf16) -> conflict-free fragment LDS
#define NSLICE 8
#define SLICE  1024      // candidates per knn slice
#define BUFCAP 112       // survivor buffer per (query, slice)

// ---------------- scratch (static device globals) ----------------
__device__ int      g_idx[NPTS * KNB];
__device__ float    g_a1[NPTS * H0D];
__device__ float    g_c1[NPTS * H0D];
__device__ float    g_x1[NPTS * H1D];
__device__ float    g_a2[NPTS * H1D];
__device__ float    g_c2[NPTS * H1D];
__device__ uint64_t g_pk[NPTS * NSLICE * KNB];   // knn per-slice partial keys

// weights: bf16 hi/lo split, transposed to [N][K]
__device__ __nv_bfloat16 g_w2t_hi[H1D * H0D],     g_w2t_lo[H1D * H0D];      // [128][64]
__device__ __nv_bfloat16 g_w3t_hi[2 * H1D * H1D], g_w3t_lo[2 * H1D * H1D];  // [2][128][128]
__device__ __nv_bfloat16 g_w4t_hi[OUTC * H1D],    g_w4t_lo[OUTC * H1D];     // [256][128]

// ---------------- helpers ----------------
__device__ __forceinline__ void bsplit(float v, __nv_bfloat16& h, __nv_bfloat16& l) {
    h = __float2bfloat16_rn(v);
    l = __float2bfloat16_rn(v - __bfloat162float(h));
}

// orderable key: uint64 '<' == (d, idx) lexicographic '<' (finite d, idx>=0)
__device__ __forceinline__ uint64_t dkey(float d, int idx) {
    uint32_t b = __float_as_uint(d);
    b = (b & 0x80000000u) ? ~b : (b | 0x80000000u);
    return ((uint64_t)b << 32) | (uint32_t)idx;
}

__device__ __forceinline__ void mma16816(float* c, const uint32_t* a, const uint32_t* b) {
    asm volatile(
        "mma.sync.aligned.m16n8k16.row.col.f32.bf16.bf16.f32 "
        "{%0,%1,%2,%3}, {%4,%5,%6,%7}, {%8,%9}, {%0,%1,%2,%3};\n"
        : "+f"(c[0]), "+f"(c[1]), "+f"(c[2]), "+f"(c[3])
        : "r"(a[0]), "r"(a[1]), "r"(a[2]), "r"(a[3]), "r"(b[0]), "r"(b[1]));
}

// ---------------------------------------------------------------------------
// weight prep (split in two so knnA stays the 4th launch -> ncu capture)
// ---------------------------------------------------------------------------
__global__ void prep_w2k(const float* __restrict__ W2) {
    int t = blockIdx.x * 256 + threadIdx.x;      // 8192 = 128n * 64k
    int n = t >> 6, k = t & 63;
    bsplit(W2[k * H1D + n], g_w2t_hi[t], g_w2t_lo[t]);
}
__global__ void prep_w34(const float* __restrict__ W3,
                         const float* __restrict__ W4) {
    int t = blockIdx.x * 256 + threadIdx.x;      // 65536 total
    if (t < 32768) {
        int half = t >> 14; int rr = t & 16383; int n = rr >> 7; int k = rr & 127;
        float v = W3[(H1D + k) * H1D + n];
        if (half == 0) v = W3[k * H1D + n] - v;
        bsplit(v, g_w3t_hi[t], g_w3t_lo[t]);
    } else {
        int r = t - 32768;
        int n = r >> 7, k = r & 127;
        bsplit(W4[k * OUTC + n], g_w4t_hi[r], g_w4t_lo[r]);
    }
}

// ---------------------------------------------------------------------------
// pre1: a1[i] = x_i @ (W1a - W1b) + b1 ; c1[j] = x_j @ W1b
// ---------------------------------------------------------------------------
__global__ void pre1_kernel(const float* __restrict__ pts,
                            const float* __restrict__ W1,
                            const float* __restrict__ b1) {
    int t = blockIdx.x * blockDim.x + threadIdx.x;
    int i = t >> 6, h = t & 63;
    float x = pts[i * 3 + 0], y = pts[i * 3 + 1], z = pts[i * 3 + 2];
    float wa0 = W1[0 * 64 + h], wa1 = W1[1 * 64 + h], wa2 = W1[2 * 64 + h];
    float wb0 = W1[3 * 64 + h], wb1 = W1[4 * 64 + h], wb2 = W1[5 * 64 + h];
    float c = fmaf(z, wb2, fmaf(y, wb1, x * wb0));
    float a = fmaf(z, wa2 - wb2, fmaf(y, wa1 - wb1, x * (wa0 - wb0))) + b1[h];
    g_a1[t] = a;
    g_c1[t] = c;
}

// ---------------------------------------------------------------------------
// KNN stage A v4: grid (256 query-tiles x 8 slices), block 256 = 32q x 8sh.
// Slice=1024 + u64-packed survivor keys -> 44.1KB smem -> 5 CTAs/SM
// (was 57KB -> 2 CTAs/SM, occ 24% -- the measured bottleneck).
// Pass 1: branchless shard-min -> tau (>= slice 8th distance: max over the
//   8 distinct shard-min candidates, which all survive -> cnt >= 8).
// Pass 2: branch-free ballot-prefix compaction; survivors stored as ONE
//   STS.64 orderable key. Key '<' == (d,idx) lex '<' == jax top_k order.
// Finish: 1 thread/query inserts its ~22 survivors into a sorted top-8 of
//   u64 keys (order-independent over the superset) -> per-(q,slice) partial.
// ---------------------------------------------------------------------------
__global__ void __launch_bounds__(256, 5)
knnA_kernel(const float* __restrict__ pts) {
    __shared__ float4   sP[SLICE];              // 16 KB
    __shared__ uint64_t sBK[32][BUFCAP];        // 28 KB
    __shared__ int      sCnt[32];

    const int tid = threadIdx.x;
    const int ql = tid >> 3, sh = tid & 7;
    const int qiw = (tid >> 3) & 3;             // query index within warp
    const int q = blockIdx.x * 32 + ql;
    const int c0 = blockIdx.y * SLICE;

    for (int j = tid; j < SLICE; j += 256) {
        float x = pts[(c0 + j) * 3 + 0];
        float y = pts[(c0 + j) * 3 + 1];
        float z = pts[(c0 + j) * 3 + 2];
        sP[j] = make_float4(x, y, z, fmaf(z, z, fmaf(y, y, x * x)));
    }
    const float qx = pts[q * 3 + 0], qy = pts[q * 3 + 1], qz = pts[q * 3 + 2];
    const float qx2 = -2.0f * qx, qy2 = -2.0f * qy, qz2 = -2.0f * qz;
    __syncthreads();

    // ---- pass 1: branchless shard min ----
    float mymin = FLT_MAX;
#pragma unroll 8
    for (int i = 0; i < SLICE / 8; ++i) {
        float4 p = sP[i * 8 + sh];
        float d = fmaf(qz2, p.z, fmaf(qy2, p.y, fmaf(qx2, p.x, p.w)));
        mymin = fminf(mymin, d);
    }
    float tau = mymin;
    tau = fmaxf(tau, __shfl_xor_sync(0xffffffffu, tau, 1));
    tau = fmaxf(tau, __shfl_xor_sync(0xffffffffu, tau, 2));
    tau = fmaxf(tau, __shfl_xor_sync(0xffffffffu, tau, 4));

    // ---- pass 2: branch-free ballot-prefix compaction, u64 key store ----
    const unsigned ltm = (1u << sh) - 1u;       // earlier-shard mask in query byte
    int cnt = 0;
#pragma unroll 8
    for (int i = 0; i < SLICE / 8; ++i) {
        int jj = i * 8 + sh;
        float4 p = sP[jj];
        float d = fmaf(qz2, p.z, fmaf(qy2, p.y, fmaf(qx2, p.x, p.w)));
        bool keep = (d <= tau);
        unsigned m = __ballot_sync(0xffffffffu, keep);
        unsigned mq = (m >> (qiw * 8)) & 0xffu;
        int slot = cnt + __popc(mq & ltm);
        if (keep && slot < BUFCAP)              // predicated STS.64 (no branch)
            sBK[ql][slot] = dkey(d, c0 + jj);
        cnt += __popc(mq);                      // uniform across the query's lanes
    }
    if (sh == 0) sCnt[ql] = cnt;
    __syncthreads();

    // ---- finish: one thread per query inserts its survivors (u64 keys) ----
    if (tid < 32) {
        int cnt2 = sCnt[tid]; if (cnt2 > BUFCAP) cnt2 = BUFCAP;
        uint64_t mk[KNB];
#pragma unroll
        for (int s = 0; s < KNB; ++s) mk[s] = 0xFFFFFFFFFFFFFFFFull;
        for (int e = 0; e < cnt2; ++e) {
            uint64_t k = sBK[tid][e];
            if (k < mk[KNB - 1]) {
                mk[KNB - 1] = k;
#pragma unroll
                for (int s = KNB - 1; s > 0; --s) {
                    if (mk[s] < mk[s - 1]) {
                        uint64_t t2 = mk[s]; mk[s] = mk[s - 1]; mk[s - 1] = t2;
                    } else break;
                }
            }
        }
        int qq = blockIdx.x * 32 + tid;
        int base = qq * (NSLICE * KNB) + blockIdx.y * KNB;
#pragma unroll
        for (int s = 0; s < KNB; ++s) g_pk[base + s] = mk[s];
    }
}

// ---------------------------------------------------------------------------
// KNN stage B: one thread per query merges the 8 slice top-8s (u64 key order).
// Every slice contributes >= 8 real survivors, so the final 8 are real.
// ---------------------------------------------------------------------------
__global__ void knnB_kernel() {
    int q = blockIdx.x * 256 + threadIdx.x;
    uint64_t mk[KNB];
#pragma unroll
    for (int s = 0; s < KNB; ++s) mk[s] = 0xFFFFFFFFFFFFFFFFull;
    int base = q * (NSLICE * KNB);
    for (int e = 0; e < NSLICE * KNB; ++e) {
        uint64_t k = g_pk[base + e];
        if (k < mk[KNB - 1]) {
            mk[KNB - 1] = k;
#pragma unroll
            for (int s = KNB - 1; s > 0; --s) {
                if (mk[s] < mk[s - 1]) {
                    uint64_t t2 = mk[s]; mk[s] = mk[s - 1]; mk[s - 1] = t2;
                } else break;
            }
        }
    }
#pragma unroll
    for (int s = 0; s < KNB; ++s) g_idx[q * KNB + s] = (int)(uint32_t)mk[s];
}

// ===========================================================================
// Tensor-core edge GEMM (unchanged from round 6/7).
// ===========================================================================

#define GEMM_CORE(KDIM, A_BUILD)                                                   \
    const int tid = threadIdx.x;                                                   \
    const int lane = tid & 31, wid = tid >> 5;                                     \
    const int g = lane >> 2, tig = lane & 3;                                       \
    const int wm = wid & 3, wn = wid >> 2;                                         \
    const int fm = tid & 127, fq = tid >> 7;                                       \
    float acc[2][8][4];                                                            \
    _Pragma("unroll") for (int mb = 0; mb < 2; ++mb)                               \
    _Pragma("unroll") for (int nt = 0; nt < 8; ++nt)                               \
    _Pragma("unroll") for (int e = 0; e < 4; ++e) acc[mb][nt][e] = 0.f;            \
    for (int kb = 0; kb < (KDIM); kb += 32) {                                      \
        { A_BUILD }                                                                \
        {   /* stage B: [n][k] rows, 16 bf16 per thread per buffer */              \
            const __nv_bfloat16* bh = Bhi_g + fm * (KDIM) + kb + fq * 16;          \
            const __nv_bfloat16* bl = Blo_g + fm * (KDIM) + kb + fq * 16;          \
            int o = fm * SA + fq * 16;                                             \
            *(uint4*)&sBhi[o]     = *(const uint4*)(bh);                           \
            *(uint4*)&sBhi[o + 8] = *(const uint4*)(bh + 8);                       \
            *(uint4*)&sBlo[o]     = *(const uint4*)(bl);                           \
            *(uint4*)&sBlo[o + 8] = *(const uint4*)(bl + 8);                       \
        }                                                                          \
        __syncthreads();                                                           \
        _Pragma("unroll")                                                          \
        for (int ks = 0; ks < 2; ++ks) {                                           \
            const int kc = ks * 16;                                                \
            _Pragma("unroll")                                                      \
            for (int t = 0; t < 3; ++t) {                                          \
                const __nv_bfloat16* Ap = (t == 2) ? sAlo : sAhi;                  \
                const __nv_bfloat16* Bp = (t == 1) ? sBlo : sBhi;                  \
                uint32_t af[2][4];                                                 \
                _Pragma("unroll")                                                  \
                for (int mb = 0; mb < 2; ++mb) {                                   \
                    int r = (wm * 32 + mb * 16 + g) * SA + kc + tig * 2;           \
                    af[mb][0] = *(const uint32_t*)(Ap + r);                        \
                    af[mb][1] = *(const uint32_t*)(Ap + r + 8 * SA);               \
                    af[mb][2] = *(const uint32_t*)(Ap + r + 8);                    \
                    af[mb][3] = *(const uint32_t*)(Ap + r + 8 * SA + 8);           \
                }                                                                  \
                uint32_t bf[8][2];                                                 \
                _Pragma("unroll")                                                  \
                for (int nt = 0; nt < 8; ++nt) {                                   \
                    int rB = (wn * 64 + nt * 8 + g) * SA + kc + tig * 2;           \
                    bf[nt][0] = *(const uint32_t*)(Bp + rB);                       \
                    bf[nt][1] = *(const uint32_t*)(Bp + rB + 8);                   \
                }                                                                  \
                _Pragma("unroll")                                                  \
                for (int mb = 0; mb < 2; ++mb)                                     \
                _Pragma("unroll")                                                  \
                for (int nt = 0; nt < 8; ++nt)                                     \
                    mma16816(acc[mb][nt], af[mb], bf[nt]);                         \
            }                                                                      \
        }                                                                          \
        __syncthreads();                                                           \
    }

#define EDGE_A_BUILD(KDIM, ASRC, CSRC)                                             \
    const float* __restrict__ arow = (ASRC) + (p0 + (fm >> 3)) * (KDIM);           \
    const float* __restrict__ crow = (CSRC) + sIdx[fm] * (KDIM);                   \
    _Pragma("unroll")                                                              \
    for (int u = 0; u < 4; ++u) {                                                  \
        float4 a = *(const float4*)(arow + kb + fq * 16 + u * 4);                  \
        float4 c = *(const float4*)(crow + kb + fq * 16 + u * 4);                  \
        float v0 = fmaxf(a.x + c.x, 0.f), v1 = fmaxf(a.y + c.y, 0.f);              \
        float v2 = fmaxf(a.z + c.z, 0.f), v3 = fmaxf(a.w + c.w, 0.f);              \
        __nv_bfloat16 h0, l0, h1, l1, h2, l2, h3, l3;                              \
        bsplit(v0, h0, l0); bsplit(v1, h1, l1);                                    \
        bsplit(v2, h2, l2); bsplit(v3, h3, l3);                                    \
        int o = fm * SA + fq * 16 + u * 4;                                         \
        __nv_bfloat162 p01; p01.x = h0; p01.y = h1;                                \
        __nv_bfloat162 p23; p23.x = h2; p23.y = h3;                                \
        *(__nv_bfloat162*)&sAhi[o] = p01; *(__nv_bfloat162*)&sAhi[o + 2] = p23;    \
        p01.x = l0; p01.y = l1; p23.x = l2; p23.y = l3;                            \
        *(__nv_bfloat162*)&sAlo[o] = p01; *(__nv_bfloat162*)&sAlo[o + 2] = p23;    \
    }

#define EDGE_POOL_EPILOGUE()                                                       \
    _Pragma("unroll")                                                              \
    for (int mb = 0; mb < 2; ++mb)                                                 \
    _Pragma("unroll")                                                              \
    for (int nt = 0; nt < 8; ++nt)                                                 \
    _Pragma("unroll")                                                              \
    for (int e = 0; e < 4; ++e) {                                                  \
        float v = acc[mb][nt][e];                                                  \
        v = fmaxf(v, __shfl_xor_sync(0xffffffffu, v, 4));                          \
        v = fmaxf(v, __shfl_xor_sync(0xffffffffu, v, 8));                          \
        v = fmaxf(v, __shfl_xor_sync(0xffffffffu, v, 16));                         \
        acc[mb][nt][e] = v;                                                        \
    }                                                                              \
    if (g == 0) {                                                                  \
        _Pragma("unroll")                                                          \
        for (int mb = 0; mb < 2; ++mb)                                             \
        _Pragma("unroll")                                                          \
        for (int nt = 0; nt < 8; ++nt)                                             \
        _Pragma("unroll")                                                          \
        for (int e = 0; e < 4; ++e) {                                              \
            int point = wm * 4 + mb * 2 + (e >> 1);                                \
            int col = wn * 64 + nt * 8 + tig * 2 + (e & 1);                        \
            sRed[point * 132 + col] = acc[mb][nt][e];                              \
        }                                                                          \
    }                                                                              \
    __syncthreads();

// ---------------------------------------------------------------------------
// edge1: x1 = relu( max_k relu(a1[i]+c1[j]) @ W2 + b2 );  K=64, N=128
// ---------------------------------------------------------------------------
__global__ void __launch_bounds__(256, 2)
edge1_kernel(const float* __restrict__ b2) {
    __shared__ __align__(16) char smraw[4 * 128 * SA * 2];
    __shared__ int sIdx[128];
    __nv_bfloat16* sAhi = (__nv_bfloat16*)smraw;
    __nv_bfloat16* sAlo = sAhi + 128 * SA;
    __nv_bfloat16* sBhi = sAlo + 128 * SA;
    __nv_bfloat16* sBlo = sBhi + 128 * SA;
    float* sRed = (float*)smraw;                   // reused after GEMM

    const int p0 = blockIdx.x * 16;
    if (threadIdx.x < 128) sIdx[threadIdx.x] = g_idx[p0 * KNB + threadIdx.x];
    __syncthreads();

    const __nv_bfloat16* Bhi_g = g_w2t_hi;
    const __nv_bfloat16* Blo_g = g_w2t_lo;

    GEMM_CORE(64, EDGE_A_BUILD(64, g_a1, g_c1))
    EDGE_POOL_EPILOGUE()

    for (int r = tid; r < 2048; r += 256) {
        int p = r >> 7, c = r & 127;
        g_x1[(p0 + p) * H1D + c] = fmaxf(sRed[p * 132 + c] + b2[c], 0.f);
    }
}

// ---------------------------------------------------------------------------
// pre2: a2 = x1 @ (W3a-W3b) + b3 ; c2 = x1 @ W3b.  M=128, N=128, K=128.
// ---------------------------------------------------------------------------
#define PRE2_A_BUILD()                                                             \
    const float* __restrict__ xrow = g_x1 + (r0 + fm) * H1D;                       \
    _Pragma("unroll")                                                              \
    for (int u = 0; u < 4; ++u) {                                                  \
        float4 a = *(const float4*)(xrow + kb + fq * 16 + u * 4);                  \
        __nv_bfloat16 h0, l0, h1, l1, h2, l2, h3, l3;                              \
        bsplit(a.x, h0, l0); bsplit(a.y, h1, l1);                                  \
        bsplit(a.z, h2, l2); bsplit(a.w, h3, l3);                                  \
        int o = fm * SA + fq * 16 + u * 4;                                         \
        __nv_bfloat162 p01; p01.x = h0; p01.y = h1;                                \
        __nv_bfloat162 p23; p23.x = h2; p23.y = h3;                                \
        *(__nv_bfloat162*)&sAhi[o] = p01; *(__nv_bfloat162*)&sAhi[o + 2] = p23;    \
        p01.x = l0; p01.y = l1; p23.x = l2; p23.y = l3;                            \
        *(__nv_bfloat162*)&sAlo[o] = p01; *(__nv_bfloat162*)&sAlo[o + 2] = p23;    \
    }

__global__ void __launch_bounds__(256, 2)
pre2_kernel(const float* __restrict__ b3) {
    __shared__ __align__(16) char smraw[4 * 128 * SA * 2];
    __nv_bfloat16* sAhi = (__nv_bfloat16*)smraw;
    __nv_bfloat16* sAlo = sAhi + 128 * SA;
    __nv_bfloat16* sBhi = sAlo + 128 * SA;
    __nv_bfloat16* sBlo = sBhi + 128 * SA;

    const int r0 = blockIdx.x * 128;
    const int half = blockIdx.y;
    const __nv_bfloat16* Bhi_g = g_w3t_hi + half * (H1D * H1D);
    const __nv_bfloat16* Blo_g = g_w3t_lo + half * (H1D * H1D);

    GEMM_CORE(128, PRE2_A_BUILD())

    float* __restrict__ outp = half ? g_c2 : g_a2;
#pragma unroll
    for (int mb = 0; mb < 2; ++mb) {
        int row = r0 + wm * 32 + mb * 16 + g;
#pragma unroll
        for (int nt = 0; nt < 8; ++nt) {
            int col = wn * 64 + nt * 8 + tig * 2;
            float bx = half ? 0.f : b3[col];
            float by = half ? 0.f : b3[col + 1];
            float2 v0 = make_float2(acc[mb][nt][0] + bx, acc[mb][nt][1] + by);
            float2 v1 = make_float2(acc[mb][nt][2] + bx, acc[mb][nt][3] + by);
            *(float2*)&outp[row * H1D + col] = v0;
            *(float2*)&outp[(row + 8) * H1D + col] = v1;
        }
    }
}

// ---------------------------------------------------------------------------
// edge2: out = max_k relu(a2[i]+c2[j]) @ W4 + b4.  K=128, N=256 (split by y).
// ---------------------------------------------------------------------------
__global__ void __launch_bounds__(256, 2)
edge2_kernel(const float* __restrict__ b4, float* __restrict__ out) {
    __shared__ __align__(16) char smraw[4 * 128 * SA * 2];
    __shared__ int sIdx[128];
    __nv_bfloat16* sAhi = (__nv_bfloat16*)smraw;
    __nv_bfloat16* sAlo = sAhi + 128 * SA;
    __nv_bfloat16* sBhi = sAlo + 128 * SA;
    __nv_bfloat16* sBlo = sBhi + 128 * SA;
    float* sRed = (float*)smraw;

    const int p0 = blockIdx.x * 16;
    const int nb = blockIdx.y * 128;
    if (threadIdx.x < 128) sIdx[threadIdx.x] = g_idx[p0 * KNB + threadIdx.x];
    __syncthreads();

    const __nv_bfloat16* Bhi_g = g_w4t_hi + nb * H1D;
    const __nv_bfloat16* Blo_g = g_w4t_lo + nb * H1D;

    GEMM_CORE(128, EDGE_A_BUILD(128, g_a2, g_c2))
    EDGE_POOL_EPILOGUE()

    for (int r = tid; r < 2048; r += 256) {
        int p = r >> 7, c = r & 127;
        out[(p0 + p) * OUTC + nb + c] = sRed[p * 132 + c] + b4[nb + c];
    }
}

// ---------------------------------------------------------------------------
extern "C" void kernel_launch(void* const* d_in, const int* in_sizes, int n_in,
                              void* d_out, int out_size) {
    const float* pts = (const float*)d_in[0];
    const float* W1  = (const float*)d_in[1];
    const float* b1  = (const float*)d_in[2];
    const float* W2  = (const float*)d_in[3];
    const float* b2  = (const float*)d_in[4];
    const float* W3  = (const float*)d_in[5];
    const float* b3  = (const float*)d_in[6];
    const float* W4  = (const float*)d_in[7];
    const float* b4  = (const float*)d_in[8];
    float* out = (float*)d_out;

    prep_w2k<<<32, 256>>>(W2);                           // 1
    prep_w34<<<256, 256>>>(W3, W4);                      // 2
    pre1_kernel<<<NPTS * H0D / 256, 256>>>(pts, W1, b1); // 3
    knnA_kernel<<<dim3(NPTS / 32, NSLICE), 256>>>(pts);  // 4 <- ncu capture slot
    knnB_kernel<<<NPTS / 256, 256>>>();                  // 5
    edge1_kernel<<<NPTS / 16, 256>>>(b2);                // 6
    pre2_kernel<<<dim3(NPTS / 128, 2), 256>>>(b3);       // 7
    edge2_kernel<<<dim3(NPTS / 16, 2), 256>>>(b4, out);  // 8
}